// round 3
// baseline (speedup 1.0000x reference)
#include <cuda_runtime.h>
#include <cuda_bf16.h>
#include <math.h>

namespace {

constexpr int B  = 256;
constexpr int L  = 128;
constexpr int H  = 512;
constexpr int H4 = 2048;

// ---------------- device state (allocation-free scratch) ----------------
__device__ float g_h[2][B * H];                          // hidden, double buffered by parity
__device__ float g_c[B * H];                             // cell
__device__ float g_enc_out[(size_t)B * L * H];           // fp32 (input to encw1 GEMM)
__device__ __nv_bfloat16 g_enc_outh[(size_t)B * L * H];  // bf16 copy (decode-phase context)
__device__ __nv_bfloat16 g_enc_w1h[(size_t)B * L * H];   // bf16 enc_out @ w1^T (decode-phase scores)
__device__ float g_ctx[B * H];                           // attention context
__device__ float g_dec_in[2][B];                         // decoder scalar input
__device__ float g_ewh4[H4 * H];                         // enc_Wh, gate-interleaved cols [n'=h*4+g][k]
__device__ float g_eb4[H4];                              // enc bias, interleaved
__device__ float g_ewi4[H4];                             // enc Wi (scalar input), interleaved
__device__ float g_dw4[H4 * 1024];                       // dec [Wi_main | Wh], interleaved rows, stride 1024
__device__ float g_db4[H4];                              // dec bias, interleaved
__device__ float g_dwi4[H4];                             // dec Wi last column (scalar input), interleaved
__device__ float g_qpart[8 * B * H];                     // split-K partials for q = h @ w2^T

// ---------------- math helpers ----------------
__device__ __forceinline__ float sigmoid_acc(float x) {
    return 1.0f / (1.0f + __expf(-x));
}
__device__ __forceinline__ float tanh_acc(float x) {
    float e = __expf(-2.0f * fabsf(x));
    float r = (1.0f - e) / (1.0f + e);
    return copysignf(r, x);
}
__device__ __forceinline__ float tanh_fast(float x) {
    float y;
    asm("tanh.approx.f32 %0, %1;" : "=f"(y) : "f"(x));
    return y;
}

// ---------------- init ----------------
__global__ void k_init() {
    int i = blockIdx.x * blockDim.x + threadIdx.x;
    int stride = gridDim.x * blockDim.x;
    for (int j = i; j < B * H; j += stride) {
        g_h[0][j] = 0.0f;
        g_c[j]    = 0.0f;
    }
    if (i < B) g_dec_in[0][i] = 0.0f;
}

// ---------------- one-time repacks: gate-interleave columns (n' = h*4 + g) ----------------
__global__ void k_repack_enc(const float* __restrict__ ewh,
                             const float* __restrict__ eb,
                             const float* __restrict__ ewi) {
    int i = blockIdx.x * blockDim.x + threadIdx.x;
    int stride = gridDim.x * blockDim.x;
    for (int j = i; j < H4 * H; j += stride) {
        int np = j >> 9;                 // n' = j / 512
        int k  = j & (H - 1);
        int hh = np >> 2, g = np & 3;
        g_ewh4[j] = ewh[(g * H + hh) * H + k];
    }
    if (i < H4) {
        int hh = i >> 2, g = i & 3;
        g_eb4[i]  = eb[g * H + hh];
        g_ewi4[i] = ewi[g * H + hh];     // enc_Wi is [2048 x 1]
    }
}

__global__ void k_repack_dec(const float* __restrict__ dwi,
                             const float* __restrict__ dwh,
                             const float* __restrict__ db) {
    int i = blockIdx.x * blockDim.x + threadIdx.x;
    int stride = gridDim.x * blockDim.x;
    for (int j = i; j < H4 * 1024; j += stride) {
        int np = j >> 10;                // n' = j / 1024
        int k  = j & 1023;
        int hh = np >> 2, g = np & 3;
        int row = g * H + hh;
        g_dw4[j] = (k < H) ? dwi[row * (H + 1) + k] : dwh[row * H + (k - H)];
    }
    if (i < H4) {
        int hh = i >> 2, g = i & 3;
        g_db4[i]  = db[g * H + hh];
        g_dwi4[i] = dwi[(g * H + hh) * (H + 1) + H];
    }
}

// ---------------- fused LSTM step: GEMM (gate-interleaved) + cell update epilogue ----------------
// z[b][n'] = A[b] @ W[n']^T ; n' quad = (i,f,g,o) of one h. Tile 64x64, micro 4x4, BK=16,
// double-buffered smem. grid = (H4/64=32, B/64=4), 256 threads.
template <int KTOT, bool DEC>
__global__ void __launch_bounds__(256) k_lstm(
    const float* __restrict__ W,      // [2048 x KTOT] interleaved
    const float* __restrict__ bias4,  // [2048] interleaved
    const float* __restrict__ wiv4,   // [2048] interleaved scalar-input weights
    const int*   __restrict__ xs,
    const int*   __restrict__ argsort,
    int t)
{
    constexpr int NT = KTOT / 16;

    __shared__ float As[2][16][68];
    __shared__ float Bs[2][16][68];

    const int tid = threadIdx.x;
    const int tx  = tid & 15;            // n quad -> one h, 4 gates
    const int ty  = tid >> 4;            // m quad
    const int n0  = blockIdx.x * 64;
    const int m0  = blockIdx.y * 64;
    const int p   = t & 1;

    const int rl = tid >> 2;             // 0..63
    const int kl = (tid & 3) * 4;        // 0,4,8,12

    const float* A0 = DEC ? g_ctx : g_h[p];
    const float* A1 = g_h[p];            // dec: h part of concat

    float acc[4][4] = {};

    auto gload = [&](int k0, float4& av, float4& wv) {
        const int k = k0 + kl;
        const float* asrc;
        if (DEC) {
            asrc = (k < H) ? (A0 + (m0 + rl) * H + k)
                           : (A1 + (m0 + rl) * H + (k - H));
        } else {
            asrc = A0 + (m0 + rl) * H + k;
        }
        av = *(const float4*)asrc;
        wv = *(const float4*)&W[(size_t)(n0 + rl) * KTOT + k];
    };
    auto sstore = [&](int buf, float4 av, float4 wv) {
        As[buf][kl + 0][rl] = av.x; As[buf][kl + 1][rl] = av.y;
        As[buf][kl + 2][rl] = av.z; As[buf][kl + 3][rl] = av.w;
        Bs[buf][kl + 0][rl] = wv.x; Bs[buf][kl + 1][rl] = wv.y;
        Bs[buf][kl + 2][rl] = wv.z; Bs[buf][kl + 3][rl] = wv.w;
    };

    {
        float4 av, wv;
        gload(0, av, wv);
        sstore(0, av, wv);
    }
    __syncthreads();

    for (int it = 0; it < NT; it++) {
        float4 av, wv;
        const bool more = (it + 1 < NT);
        if (more) gload((it + 1) * 16, av, wv);

        const int cb = it & 1;
#pragma unroll
        for (int k = 0; k < 16; k++) {
            float4 a = *(const float4*)&As[cb][k][ty * 4];
            float4 b = *(const float4*)&Bs[cb][k][tx * 4];
            acc[0][0] += a.x * b.x; acc[0][1] += a.x * b.y; acc[0][2] += a.x * b.z; acc[0][3] += a.x * b.w;
            acc[1][0] += a.y * b.x; acc[1][1] += a.y * b.y; acc[1][2] += a.y * b.z; acc[1][3] += a.y * b.w;
            acc[2][0] += a.z * b.x; acc[2][1] += a.z * b.y; acc[2][2] += a.z * b.z; acc[2][3] += a.z * b.w;
            acc[3][0] += a.w * b.x; acc[3][1] += a.w * b.y; acc[3][2] += a.w * b.z; acc[3][3] += a.w * b.w;
        }
        if (more) sstore(cb ^ 1, av, wv);  // writes buffer != cb: no race with readers
        __syncthreads();
    }

    // ---- epilogue: full LSTM cell update for (b = m0+ty*4+r, h = n0/4 + tx) ----
    const int h_idx = (n0 >> 2) + tx;
    const float4 bv = *(const float4*)&bias4[n0 + tx * 4];
    const float4 wv = *(const float4*)&wiv4[n0 + tx * 4];

#pragma unroll
    for (int r = 0; r < 4; r++) {
        const int b = m0 + ty * 4 + r;
        const float xb = DEC ? g_dec_in[p][b] : (float)xs[b * L + t];
        const float zi = acc[r][0] + bv.x + xb * wv.x;
        const float zf = acc[r][1] + bv.y + xb * wv.y;
        const float zg = acc[r][2] + bv.z + xb * wv.z;
        const float zo = acc[r][3] + bv.w + xb * wv.w;
        const int ci = b * H + h_idx;
        const float c  = sigmoid_acc(zf) * g_c[ci] + sigmoid_acc(zi) * tanh_acc(zg);
        const float hn = sigmoid_acc(zo) * tanh_acc(c);
        g_c[ci] = c;
        g_h[p ^ 1][ci] = hn;
        if (!DEC) {
            const size_t eo = ((size_t)b * L + t) * H + h_idx;
            g_enc_out[eo]  = hn;
            g_enc_outh[eo] = __float2bfloat16_rn(hn);
        }
    }

    // teacher-forced next decoder input (one writer per b)
    if (DEC && blockIdx.x == 0 && tx == 0) {
#pragma unroll
        for (int r = 0; r < 4; r++) {
            const int b = m0 + ty * 4 + r;
            g_dec_in[p ^ 1][b] = (float)xs[b * L + argsort[b * L + t]];
        }
    }
}

// ---------------- q-proj split-K GEMM: qpart[kz] = h @ w2^T over K-chunk ----------------
// grid = (8, 4, 8) = 256 CTAs, 256 threads, tile 64x64, micro 4x4.
__global__ void __launch_bounds__(256) k_qproj(
    const float* __restrict__ W,    // w2 [512 x 512]
    const float* __restrict__ A,    // h  [256 x 512]
    float* __restrict__ part)       // [8][256][512]
{
    constexpr int KC = 64;          // 512 / 8
    constexpr int NT = KC / 16;

    __shared__ float As[2][16][68];
    __shared__ float Bs[2][16][68];

    const int tid = threadIdx.x;
    const int tx  = tid & 15;
    const int ty  = tid >> 4;
    const int n0  = blockIdx.x * 64;
    const int m0  = blockIdx.y * 64;
    const int kbase = blockIdx.z * KC;

    const int rl = tid >> 2;
    const int kl = (tid & 3) * 4;

    float acc[4][4] = {};

    auto gload = [&](int k0, float4& av, float4& wv) {
        const int k = k0 + kl;
        av = *(const float4*)&A[(m0 + rl) * H + k];
        wv = *(const float4*)&W[(size_t)(n0 + rl) * H + k];
    };
    auto sstore = [&](int buf, float4 av, float4 wv) {
        As[buf][kl + 0][rl] = av.x; As[buf][kl + 1][rl] = av.y;
        As[buf][kl + 2][rl] = av.z; As[buf][kl + 3][rl] = av.w;
        Bs[buf][kl + 0][rl] = wv.x; Bs[buf][kl + 1][rl] = wv.y;
        Bs[buf][kl + 2][rl] = wv.z; Bs[buf][kl + 3][rl] = wv.w;
    };

    {
        float4 av, wv;
        gload(kbase, av, wv);
        sstore(0, av, wv);
    }
    __syncthreads();

    for (int it = 0; it < NT; it++) {
        float4 av, wv;
        const bool more = (it + 1 < NT);
        if (more) gload(kbase + (it + 1) * 16, av, wv);
        const int cb = it & 1;
#pragma unroll
        for (int k = 0; k < 16; k++) {
            float4 a = *(const float4*)&As[cb][k][ty * 4];
            float4 b = *(const float4*)&Bs[cb][k][tx * 4];
            acc[0][0] += a.x * b.x; acc[0][1] += a.x * b.y; acc[0][2] += a.x * b.z; acc[0][3] += a.x * b.w;
            acc[1][0] += a.y * b.x; acc[1][1] += a.y * b.y; acc[1][2] += a.y * b.z; acc[1][3] += a.y * b.w;
            acc[2][0] += a.z * b.x; acc[2][1] += a.z * b.y; acc[2][2] += a.z * b.z; acc[2][3] += a.z * b.w;
            acc[3][0] += a.w * b.x; acc[3][1] += a.w * b.y; acc[3][2] += a.w * b.z; acc[3][3] += a.w * b.w;
        }
        if (more) sstore(cb ^ 1, av, wv);
        __syncthreads();
    }

    float* dst = part + (size_t)blockIdx.z * (B * H);
#pragma unroll
    for (int i = 0; i < 4; i++) {
        float4 o = make_float4(acc[i][0], acc[i][1], acc[i][2], acc[i][3]);
        *(float4*)&dst[(size_t)(m0 + ty * 4 + i) * H + n0 + tx * 4] = o;
    }
}

// ---------------- enc_w1 = enc_out @ w1^T -> bf16  (M=32768, N=512, K=512) ----------------
__global__ void __launch_bounds__(256) k_encw1(const float* __restrict__ w1) {
    __shared__ float As[16][68];
    __shared__ float Bs[16][68];

    const int tid = threadIdx.x;
    const int tx = tid & 15;
    const int ty = tid >> 4;
    const int n0 = blockIdx.x * 64;
    const int m0 = blockIdx.y * 64;

    const int rl = tid >> 2;
    const int kl = (tid & 3) * 4;

    float acc[4][4] = {};

    for (int k0 = 0; k0 < H; k0 += 16) {
        __syncthreads();
        {
            float4 av = *(const float4*)&g_enc_out[(size_t)(m0 + rl) * H + k0 + kl];
            As[kl + 0][rl] = av.x; As[kl + 1][rl] = av.y;
            As[kl + 2][rl] = av.z; As[kl + 3][rl] = av.w;
            float4 bv = *(const float4*)&w1[(n0 + rl) * H + k0 + kl];
            Bs[kl + 0][rl] = bv.x; Bs[kl + 1][rl] = bv.y;
            Bs[kl + 2][rl] = bv.z; Bs[kl + 3][rl] = bv.w;
        }
        __syncthreads();
#pragma unroll
        for (int k = 0; k < 16; k++) {
            float4 a = *(const float4*)&As[k][ty * 4];
            float4 w = *(const float4*)&Bs[k][tx * 4];
            acc[0][0] += a.x * w.x; acc[0][1] += a.x * w.y; acc[0][2] += a.x * w.z; acc[0][3] += a.x * w.w;
            acc[1][0] += a.y * w.x; acc[1][1] += a.y * w.y; acc[1][2] += a.y * w.z; acc[1][3] += a.y * w.w;
            acc[2][0] += a.z * w.x; acc[2][1] += a.z * w.y; acc[2][2] += a.z * w.z; acc[2][3] += a.z * w.w;
            acc[3][0] += a.w * w.x; acc[3][1] += a.w * w.y; acc[3][2] += a.w * w.z; acc[3][3] += a.w * w.w;
        }
    }
#pragma unroll
    for (int i = 0; i < 4; i++) {
        __nv_bfloat162 p0 = __floats2bfloat162_rn(acc[i][0], acc[i][1]);
        __nv_bfloat162 p1 = __floats2bfloat162_rn(acc[i][2], acc[i][3]);
        uint2 pk = make_uint2(*(unsigned*)&p0, *(unsigned*)&p1);
        *(uint2*)&g_enc_w1h[(size_t)(m0 + ty * 4 + i) * H + n0 + tx * 4] = pk;
    }
}

// ---------------- attention: q-reduce + scores + softmax/log_softmax + context ----------------
// One block per batch element. All big reads are bf16 (L2-resident working set).
__global__ void __launch_bounds__(256) k_attn(const float* __restrict__ vt,
                                              float* __restrict__ out, int t) {
    __shared__ float q_s[H];
    __shared__ float vt_s[H];
    __shared__ float sc[L];
    __shared__ float aj[L];

    const int b = blockIdx.x;
    const int tid = threadIdx.x;
    const int lane = tid & 31;
    const int w = tid >> 5;

    for (int i = tid; i < H; i += 256) {
        float s = 0.0f;
#pragma unroll
        for (int sp = 0; sp < 8; sp++)
            s += g_qpart[(size_t)sp * (B * H) + b * H + i];
        q_s[i]  = s;
        vt_s[i] = vt[i];
    }
    __syncthreads();

    // scores[l] = sum_h vt[h] * tanh(enc_w1[b,l,h] + q[h]); warp w handles 16 l's
#pragma unroll 1
    for (int li = 0; li < 16; li++) {
        const int l = w * 16 + li;
        const uint4* e8 = (const uint4*)(g_enc_w1h + (size_t)(b * L + l) * H);
        float s = 0.f;
#pragma unroll
        for (int j = 0; j < 2; j++) {
            const int base = (lane + j * 32) * 8;
            uint4 u = e8[lane + j * 32];
            float4 q0 = *(const float4*)&q_s[base];
            float4 q1 = *(const float4*)&q_s[base + 4];
            float4 v0 = *(const float4*)&vt_s[base];
            float4 v1 = *(const float4*)&vt_s[base + 4];
            float2 e0 = __bfloat1622float2(*(__nv_bfloat162*)&u.x);
            float2 e1 = __bfloat1622float2(*(__nv_bfloat162*)&u.y);
            float2 e2 = __bfloat1622float2(*(__nv_bfloat162*)&u.z);
            float2 e3 = __bfloat1622float2(*(__nv_bfloat162*)&u.w);
            s += v0.x * tanh_fast(e0.x + q0.x);
            s += v0.y * tanh_fast(e0.y + q0.y);
            s += v0.z * tanh_fast(e1.x + q0.z);
            s += v0.w * tanh_fast(e1.y + q0.w);
            s += v1.x * tanh_fast(e2.x + q1.x);
            s += v1.y * tanh_fast(e2.y + q1.y);
            s += v1.z * tanh_fast(e3.x + q1.z);
            s += v1.w * tanh_fast(e3.y + q1.w);
        }
#pragma unroll
        for (int o = 16; o > 0; o >>= 1) s += __shfl_xor_sync(0xffffffffu, s, o);
        if (lane == 0) sc[l] = s;
    }
    __syncthreads();

    if (w == 0) {
        float sv[4];
        float m = -1e30f;
#pragma unroll
        for (int k = 0; k < 4; k++) { sv[k] = sc[lane * 4 + k]; m = fmaxf(m, sv[k]); }
#pragma unroll
        for (int o = 16; o > 0; o >>= 1) m = fmaxf(m, __shfl_xor_sync(0xffffffffu, m, o));
        float e[4], sum = 0.f;
#pragma unroll
        for (int k = 0; k < 4; k++) { e[k] = __expf(sv[k] - m); sum += e[k]; }
#pragma unroll
        for (int o = 16; o > 0; o >>= 1) sum += __shfl_xor_sync(0xffffffffu, sum, o);
        const float ls  = __logf(sum);
        const float inv = 1.0f / sum;
        float* orow = out + ((size_t)b * L + t) * L;
#pragma unroll
        for (int k = 0; k < 4; k++) {
            orow[lane * 4 + k] = sv[k] - m - ls;
            aj[lane * 4 + k]   = e[k] * inv;
        }
    }
    __syncthreads();

    // context[h] = sum_l aj[l] * enc_out[b,l,h] (bf16 source, fp32 accumulate)
    const int h2 = tid * 2;
    float ax = 0.f, ay = 0.f;
    const __nv_bfloat162* base =
        (const __nv_bfloat162*)(g_enc_outh + (size_t)b * L * H + h2);
#pragma unroll 4
    for (int l = 0; l < L; l++) {
        const float a = aj[l];
        float2 v = __bfloat1622float2(base[(size_t)l * (H / 2)]);
        ax += a * v.x;
        ay += a * v.y;
    }
    g_ctx[b * H + h2]     = ax;
    g_ctx[b * H + h2 + 1] = ay;
}

}  // namespace

extern "C" void kernel_launch(void* const* d_in, const int* in_sizes, int n_in,
                              void* d_out, int out_size) {
    (void)in_sizes; (void)n_in; (void)out_size;
    const int*   xs      = (const int*)d_in[0];
    const int*   argsort = (const int*)d_in[2];
    const float* enc_Wi  = (const float*)d_in[3];
    const float* enc_Wh  = (const float*)d_in[4];
    const float* enc_b   = (const float*)d_in[5];
    const float* dec_Wi  = (const float*)d_in[6];
    const float* dec_Wh  = (const float*)d_in[7];
    const float* dec_b   = (const float*)d_in[8];
    const float* w1      = (const float*)d_in[9];
    const float* w2      = (const float*)d_in[10];
    const float* vt      = (const float*)d_in[11];
    float* out = (float*)d_out;

    // device-global addresses (host-side symbol queries; no allocation)
    float *p_h, *p_ewh4, *p_eb4, *p_ewi4, *p_dw4, *p_db4, *p_dwi4, *p_qpart;
    cudaGetSymbolAddress((void**)&p_h,     g_h);
    cudaGetSymbolAddress((void**)&p_ewh4,  g_ewh4);
    cudaGetSymbolAddress((void**)&p_eb4,   g_eb4);
    cudaGetSymbolAddress((void**)&p_ewi4,  g_ewi4);
    cudaGetSymbolAddress((void**)&p_dw4,   g_dw4);
    cudaGetSymbolAddress((void**)&p_db4,   g_db4);
    cudaGetSymbolAddress((void**)&p_dwi4,  g_dwi4);
    cudaGetSymbolAddress((void**)&p_qpart, g_qpart);

    k_init<<<128, 256>>>();
    k_repack_enc<<<256, 256>>>(enc_Wh, enc_b, enc_Wi);
    k_repack_dec<<<256, 256>>>(dec_Wi, dec_Wh, dec_b);

    const dim3 lstm_grid(H4 / 64, B / 64);      // (32, 4) = 128 CTAs
    const dim3 q_grid(H / 64, B / 64, 8);       // (8, 4, 8) = 256 CTAs

    // ---- encoder: 128 fused LSTM steps (one launch each) ----
    for (int t = 0; t < L; t++) {
        k_lstm<512, false><<<lstm_grid, 256>>>(p_ewh4, p_eb4, p_ewi4, xs, nullptr, t);
    }

    // ---- hoisted projection enc_w1 = enc_out @ w1^T (bf16 out) ----
    k_encw1<<<dim3(H / 64, (B * L) / 64), 256>>>(w1);

    // ---- decoder: 128 steps of q-proj -> attention -> fused LSTM ----
    for (int t = 0; t < L; t++) {
        const float* hp = p_h + (size_t)(t & 1) * (B * H);
        k_qproj<<<q_grid, 256>>>(w2, hp, p_qpart);
        k_attn<<<B, 256>>>(vt, out, t);
        k_lstm<1024, true><<<lstm_grid, 256>>>(p_dw4, p_db4, p_dwi4, xs, argsort, t);
    }
}